// round 12
// baseline (speedup 1.0000x reference)
#include <cuda_runtime.h>
#include <cuda_bf16.h>
#include <cstdint>

// Dequant: out[r][c] = (float)q[r][c] * row_stats[r] * (1/127)
// ROWS = COLS = 8192, int32 in -> fp32 out. Pure streaming: 512 MiB total.
//
// R12: 256-bit global accesses (Blackwell-only ld/st.global.v8.b32 ->
// LDG.E.256 / STG.E.256; ptxas never emits these from C++). Same measured-
// best schedule as R3/R6/R8 (one block == one row, uniform per-block scale,
// front-batched loads, .cs both directions, 32 elements/thread) but with
// half the LDG/STG instruction count: 4x 32B loads + 4x 32B stores per
// thread instead of 8x 16B each. LSU dispatch work halved at equal register
// cost; L1tex wavefront count unchanged (nL=2 per LDG).

#define TPB 256
// Each thread: 4 x 32B = 128 B; block covers 256*128 B = 32 KB = one row.

__device__ __forceinline__ void ldg256_cs(const void* p, uint32_t r[8]) {
    asm volatile("ld.global.cs.v8.b32 {%0,%1,%2,%3,%4,%5,%6,%7}, [%8];"
                 : "=r"(r[0]), "=r"(r[1]), "=r"(r[2]), "=r"(r[3]),
                   "=r"(r[4]), "=r"(r[5]), "=r"(r[6]), "=r"(r[7])
                 : "l"(p));
}

__device__ __forceinline__ void stg256_cs(void* p, const uint32_t r[8]) {
    asm volatile("st.global.cs.v8.b32 [%0], {%1,%2,%3,%4,%5,%6,%7,%8};"
                 :: "l"(p),
                    "r"(r[0]), "r"(r[1]), "r"(r[2]), "r"(r[3]),
                    "r"(r[4]), "r"(r[5]), "r"(r[6]), "r"(r[7])
                 : "memory");
}

__global__ void __launch_bounds__(TPB, 6)
dequant_kernel(const int* __restrict__ q,
               const float* __restrict__ row_stats,
               float* __restrict__ out)
{
    // Uniform per-block scale: block r handles row r.
    const float scale = __ldg(&row_stats[blockIdx.x]) * (1.0f / 127.0f);

    // Element base: row*8192 + thread*8; stride between j-chunks: TPB*8 elems.
    const size_t base = (size_t)blockIdx.x * 8192 + (size_t)threadIdx.x * 8;

    // Front-batch 4 independent LDG.E.256.
    uint32_t v[4][8];
#pragma unroll
    for (int j = 0; j < 4; j++)
        ldg256_cs(q + base + (size_t)j * (TPB * 8), v[j]);

#pragma unroll
    for (int j = 0; j < 4; j++) {
        uint32_t r[8];
#pragma unroll
        for (int k = 0; k < 8; k++)
            r[k] = __float_as_uint((float)(int)v[j][k] * scale);
        stg256_cs(out + base + (size_t)j * (TPB * 8), r);
    }
}

extern "C" void kernel_launch(void* const* d_in, const int* in_sizes, int n_in,
                              void* d_out, int out_size)
{
    const int*   q         = (const int*)d_in[0];    // int32 [8192,8192]
    const float* row_stats = (const float*)d_in[1];  // fp32  [8192]
    float*       out       = (float*)d_out;

    const int rows = in_sizes[1];                    // 8192 blocks, one per row

    dequant_kernel<<<rows, TPB>>>(q, row_stats, out);
}

// round 13
// speedup vs baseline: 1.0008x; 1.0008x over previous
#include <cuda_runtime.h>
#include <cuda_bf16.h>
#include <cstdint>

// Dequant: out[r][c] = (float)q[r][c] * row_stats[r] * (1/127)
// ROWS = COLS = 8192, int32 in -> fp32 out. Pure streaming: 512 MiB total.
//
// FINAL — measured-best config, reproduced 6x (kernel 73.9-75.2us,
// end-to-end 82.0us). Exhaustive sweep (kernel us):
//   width/MLP: 128b x1 82.5 | x4 74.5 | x8 73.9 | 256b x4 75.2  (saturated)
//   stores:    .cs 73.9 | .wt 75.3 | default 75.5
//   layout:    4KB-strided 73.9 | contiguous-per-warp 75.2 (LTS addr hash
//              defeats software DRAM-locality schemes, per B300_MICROARCH)
//   grid:      oversubscribed 8192 CTAs 73.9 | persistent 912 CTAs 78.9
//              (oversubscription IS the latency hider; persistent loop
//               collapses MLP to 0 at every row seam)
// Config: one block == one row (256 thr x 8 int4 = 8192 cols), uniform
// per-block scale (single __ldg), 8 front-batched LDG.E.128 (MLP=8),
// .cs streaming hints on both loads and stores.
// Sits at 80-82% DRAM-active (~6.4-6.5 TB/s): the B300 mixed 1:1
// read/write HBM-stream ceiling. Traffic is fixed by the I/O contract
// (int32 in, fp32 out) — no format freedom. Roofline reached.

#define VPT 8                         // int4 vectors per thread
#define TPB 256                       // TPB*VPT = 2048 vecs = 8192 cols = 1 row

__global__ void __launch_bounds__(TPB, 6)
dequant_kernel(const int4* __restrict__ q,
               const float* __restrict__ row_stats,
               float4* __restrict__ out)
{
    // Uniform per-block scale: block r handles row r.
    const float scale = __ldg(&row_stats[blockIdx.x]) * (1.0f / 127.0f);

    const int base = blockIdx.x * (TPB * VPT) + threadIdx.x;

    // Front-batch 8 independent LDG.E.128 (MLP=8), streaming hint.
    int4 v[VPT];
#pragma unroll
    for (int j = 0; j < VPT; j++)
        v[j] = __ldcs(&q[base + j * TPB]);

#pragma unroll
    for (int j = 0; j < VPT; j++) {
        float4 r;
        r.x = (float)v[j].x * scale;
        r.y = (float)v[j].y * scale;
        r.z = (float)v[j].z * scale;
        r.w = (float)v[j].w * scale;
        __stcs(&out[base + j * TPB], r);   // streaming store (measured best)
    }
}

extern "C" void kernel_launch(void* const* d_in, const int* in_sizes, int n_in,
                              void* d_out, int out_size)
{
    const int4*  q         = (const int4*)d_in[0];   // int32 [8192,8192]
    const float* row_stats = (const float*)d_in[1];  // fp32  [8192]
    float4*      out       = (float4*)d_out;

    const int rows = in_sizes[1];                    // 8192 blocks, one per row

    dequant_kernel<<<rows, TPB>>>(q, row_stats, out);
}